// round 2
// baseline (speedup 1.0000x reference)
#include <cuda_runtime.h>
#include <math.h>

#define NPT 3000
#define BB 2
#define CCH 128
#define CH 64
#define LL 6
#define EPSBN 1e-5f
#define ATT_SCALE 0.08838834764831845f  // 1/sqrt(128)

// ---------------- device scratch (static, no runtime alloc) ----------------
__device__ float g_x[BB*CCH*NPT];
__device__ float g_y[BB*CCH*NPT];
__device__ float g_q[BB*CCH*NPT];
__device__ float g_k[BB*CCH*NPT];
__device__ float g_v[BB*CCH*NPT];
__device__ float g_m[BB*CCH*NPT];
__device__ float g_h[BB*CH*NPT];
__device__ float g_P[(size_t)BB*NPT*NPT];   // 72 MB logits/probs
__device__ float g_scl[CCH];
__device__ float g_shf[CCH];

// ---------------- init embedding: corr_pos [B,N,6] -> x [B,C,N] ----------------
__global__ void init_conv_kernel(const float* __restrict__ corr, const float* __restrict__ W,
                                 const float* __restrict__ bias, float* __restrict__ X)
{
    __shared__ float Ws[CCH*6];
    __shared__ float bs[CCH];
    int tid = threadIdx.x;
    for (int i = tid; i < CCH*6; i += blockDim.x) Ws[i] = W[i];
    for (int i = tid; i < CCH;   i += blockDim.x) bs[i] = bias[i];
    __syncthreads();
    int idx = blockIdx.x * blockDim.x + tid;
    if (idx >= BB*NPT) return;
    int b = idx / NPT, n = idx - b*NPT;
    float cp[6];
#pragma unroll
    for (int j = 0; j < 6; j++) cp[j] = corr[(size_t)idx*6 + j];
    for (int co = 0; co < CCH; co++) {
        float a = bs[co];
#pragma unroll
        for (int j = 0; j < 6; j++) a += Ws[co*6 + j] * cp[j];
        X[((size_t)b*CCH + co)*NPT + n] = a;
    }
}

// ---------------- pointwise conv (GEMM): Y[b,co,n] = sum_ci W[co,ci] X[b,ci,n] + bias ----
// 64x64 tile, 4x4 per-thread, inner over Cin (multiple of 32).
template<bool RELU, bool RESID>
__global__ void conv_kernel(const float* __restrict__ X, const float* __restrict__ W,
                            const float* __restrict__ bias, const float* __restrict__ R,
                            float* __restrict__ Y, int Cin, int Cout)
{
    __shared__ float Ws[32][64];
    __shared__ float Xs[32][64];
    int tid = threadIdx.x;
    int b  = blockIdx.z;
    int n0 = blockIdx.x * 64;
    int c0 = blockIdx.y * 64;
    float acc[4][4] = {};
    int m0  = (tid >> 4) << 2;   // cout sub-tile
    int nn0 = (tid & 15) << 2;   // n sub-tile

    for (int kt = 0; kt < Cin; kt += 32) {
        __syncthreads();
#pragma unroll
        for (int t = 0; t < 2; t++) {
            int f = tid*2 + t;
            int kk = f >> 4, jj = (f & 15) << 2;
            float4 v = make_float4(0.f, 0.f, 0.f, 0.f);
            if (n0 + jj < NPT)
                v = *(const float4*)&X[((size_t)b*Cin + kt + kk)*NPT + n0 + jj];
            *(float4*)&Xs[kk][jj] = v;
        }
#pragma unroll
        for (int t = 0; t < 2; t++) {
            int f = tid*2 + t;
            int m = f >> 3, k4 = (f & 7) << 2;
            float4 w = make_float4(0.f, 0.f, 0.f, 0.f);
            if (c0 + m < Cout)
                w = *(const float4*)&W[(size_t)(c0 + m)*Cin + kt + k4];
            Ws[k4+0][m] = w.x; Ws[k4+1][m] = w.y; Ws[k4+2][m] = w.z; Ws[k4+3][m] = w.w;
        }
        __syncthreads();
#pragma unroll
        for (int kk = 0; kk < 32; kk++) {
            float4 a4 = *(const float4*)&Ws[kk][m0];
            float4 b4 = *(const float4*)&Xs[kk][nn0];
            float av[4] = {a4.x, a4.y, a4.z, a4.w};
            float bv[4] = {b4.x, b4.y, b4.z, b4.w};
#pragma unroll
            for (int mi = 0; mi < 4; mi++)
#pragma unroll
                for (int ni = 0; ni < 4; ni++)
                    acc[mi][ni] += av[mi] * bv[ni];
        }
    }

#pragma unroll
    for (int mi = 0; mi < 4; mi++) {
        int co = c0 + m0 + mi;
        if (co >= Cout) continue;
        float bv = bias[co];
#pragma unroll
        for (int ni = 0; ni < 4; ni++) {
            int n = n0 + nn0 + ni;
            if (n >= NPT) continue;
            float v = acc[mi][ni] + bv;
            size_t oi = ((size_t)b*Cout + co)*NPT + n;
            if (RESID) v += R[oi];
            if (RELU)  v = fmaxf(v, 0.f);
            Y[oi] = v;
        }
    }
}

// ---------------- BN batch stats -> per-channel affine (scale, shift) ----------------
__global__ void bn_stats_kernel(const float* __restrict__ Y, const float* __restrict__ g,
                                const float* __restrict__ beta, float* __restrict__ scl,
                                float* __restrict__ shf, int Cc)
{
    __shared__ float s1[256], s2[256];
    int c = blockIdx.x, tid = threadIdx.x;
    float a = 0.f, b2 = 0.f;
    for (int idx = tid; idx < BB*NPT; idx += 256) {
        int b = idx / NPT, n = idx - b*NPT;
        float v = Y[((size_t)b*Cc + c)*NPT + n];
        a += v; b2 += v*v;
    }
    s1[tid] = a; s2[tid] = b2;
    __syncthreads();
    for (int o = 128; o > 0; o >>= 1) {
        if (tid < o) { s1[tid] += s1[tid+o]; s2[tid] += s2[tid+o]; }
        __syncthreads();
    }
    if (tid == 0) {
        float inv = 1.f / (float)(BB*NPT);
        float m = s1[0] * inv;
        float var = s2[0] * inv - m*m;
        float rs = rsqrtf(var + EPSBN);
        scl[c] = g[c] * rs;
        shf[c] = beta[c] - m * g[c] * rs;
    }
}

__global__ void affine_relu_kernel(const float* __restrict__ Y, const float* __restrict__ scl,
                                   const float* __restrict__ shf, float* __restrict__ X, int Cc)
{
    int idx = blockIdx.x * blockDim.x + threadIdx.x;
    int total = BB * Cc * NPT;
    if (idx >= total) return;
    int c = (idx / NPT) % Cc;
    X[idx] = fmaxf(fmaf(scl[c], Y[idx], shf[c]), 0.f);
}

// ---------------- scores GEMM: P[b,o,i] = sc(o,i) * SCALE * sum_c Q[c,o]K[c,i] --------
__global__ void gemm_scores_kernel(const float* __restrict__ Q, const float* __restrict__ K,
                                   const float* __restrict__ src, const float* __restrict__ tgt,
                                   float* __restrict__ P)
{
    __shared__ float Qs[32][64];
    __shared__ float Ks[32][64];
    __shared__ float pO[64][6];
    __shared__ float pI[64][6];
    int tid = threadIdx.x;
    int b  = blockIdx.z;
    int o0 = blockIdx.x * 64;
    int i0 = blockIdx.y * 64;

    if (tid < 128) {
        int r = tid & 63;
        bool isI = tid >= 64;
        int n = (isI ? i0 : o0) + r;
        float* dst = isI ? pI[r] : pO[r];
        if (n < NPT) {
#pragma unroll
            for (int j = 0; j < 3; j++) {
                dst[j]     = src[((size_t)b*NPT + n)*3 + j];
                dst[3 + j] = tgt[((size_t)b*NPT + n)*3 + j];
            }
        } else {
#pragma unroll
            for (int j = 0; j < 6; j++) dst[j] = 0.f;
        }
    }

    float acc[4][4] = {};
    int m0  = (tid >> 4) << 2;   // o sub
    int nn0 = (tid & 15) << 2;   // i sub

    for (int kt = 0; kt < CCH; kt += 32) {
        __syncthreads();
#pragma unroll
        for (int t = 0; t < 2; t++) {
            int f = tid*2 + t;
            int kk = f >> 4, jj = (f & 15) << 2;
            float4 qv = make_float4(0.f,0.f,0.f,0.f);
            float4 kv = make_float4(0.f,0.f,0.f,0.f);
            if (o0 + jj < NPT) qv = *(const float4*)&Q[((size_t)b*CCH + kt + kk)*NPT + o0 + jj];
            if (i0 + jj < NPT) kv = *(const float4*)&K[((size_t)b*CCH + kt + kk)*NPT + i0 + jj];
            *(float4*)&Qs[kk][jj] = qv;
            *(float4*)&Ks[kk][jj] = kv;
        }
        __syncthreads();
#pragma unroll
        for (int kk = 0; kk < 32; kk++) {
            float4 a4 = *(const float4*)&Qs[kk][m0];
            float4 b4 = *(const float4*)&Ks[kk][nn0];
            float av[4] = {a4.x, a4.y, a4.z, a4.w};
            float bv[4] = {b4.x, b4.y, b4.z, b4.w};
#pragma unroll
            for (int mi = 0; mi < 4; mi++)
#pragma unroll
                for (int ni = 0; ni < 4; ni++)
                    acc[mi][ni] += av[mi] * bv[ni];
        }
    }

#pragma unroll
    for (int mi = 0; mi < 4; mi++) {
        int o = o0 + m0 + mi;
        if (o >= NPT) continue;
#pragma unroll
        for (int ni = 0; ni < 4; ni++) {
            int i = i0 + nn0 + ni;
            if (i >= NPT) continue;
            float dx = pO[m0+mi][0] - pI[nn0+ni][0];
            float dy = pO[m0+mi][1] - pI[nn0+ni][1];
            float dz = pO[m0+mi][2] - pI[nn0+ni][2];
            float ds = sqrtf(dx*dx + dy*dy + dz*dz);
            dx = pO[m0+mi][3] - pI[nn0+ni][3];
            dy = pO[m0+mi][4] - pI[nn0+ni][4];
            dz = pO[m0+mi][5] - pI[nn0+ni][5];
            float dt = sqrtf(dx*dx + dy*dy + dz*dz);
            float d = ds - dt;
            float sc = fmaxf(1.f - d*d, 0.f);
            P[((size_t)b*NPT + o)*NPT + i] = sc * acc[mi][ni] * ATT_SCALE;
        }
    }
}

// ---------------- row softmax in-place over last dim of P [B,N,N] ----------------
__global__ void softmax_kernel(float* __restrict__ P)
{
    __shared__ float row[NPT];
    __shared__ float red[9];
    int o = blockIdx.x, b = blockIdx.y;
    int tid = threadIdx.x;
    float* base = P + ((size_t)b*NPT + o)*NPT;

    float mx = -3.4e38f;
    for (int i = tid*4; i < NPT; i += 1024) {
        float4 v = *(const float4*)&base[i];
        *(float4*)&row[i] = v;
        mx = fmaxf(mx, fmaxf(fmaxf(v.x, v.y), fmaxf(v.z, v.w)));
    }
#pragma unroll
    for (int s = 16; s; s >>= 1) mx = fmaxf(mx, __shfl_xor_sync(0xffffffffu, mx, s));
    int wid = tid >> 5, lane = tid & 31;
    if (lane == 0) red[wid] = mx;
    __syncthreads();
    if (tid == 0) {
        float m = red[0];
        for (int w = 1; w < 8; w++) m = fmaxf(m, red[w]);
        red[8] = m;
    }
    __syncthreads();
    mx = red[8];

    float sum = 0.f;
    for (int i = tid*4; i < NPT; i += 1024) {
        float4 v = *(float4*)&row[i];
        v.x = __expf(v.x - mx); v.y = __expf(v.y - mx);
        v.z = __expf(v.z - mx); v.w = __expf(v.w - mx);
        *(float4*)&row[i] = v;
        sum += v.x + v.y + v.z + v.w;
    }
#pragma unroll
    for (int s = 16; s; s >>= 1) sum += __shfl_xor_sync(0xffffffffu, sum, s);
    __syncthreads();
    if (lane == 0) red[wid] = sum;
    __syncthreads();
    if (tid == 0) {
        float s = 0.f;
        for (int w = 0; w < 8; w++) s += red[w];
        red[8] = s;
    }
    __syncthreads();
    float inv = 1.f / red[8];

    for (int i = tid*4; i < NPT; i += 1024) {
        float4 v = *(float4*)&row[i];
        v.x *= inv; v.y *= inv; v.z *= inv; v.w *= inv;
        *(float4*)&base[i] = v;
    }
}

// ---------------- msg GEMM (NT): M[b,c,o] = sum_i V[b,c,i] * P[b,o,i] ----------------
__global__ void gemm_msg_kernel(const float* __restrict__ V, const float* __restrict__ P,
                                float* __restrict__ M)
{
    __shared__ float As[64][36];  // V rows (c), k chunk of 32 (pad 36 keeps 16B align, 2-way max)
    __shared__ float Bs[64][36];  // P rows (o)
    int tid = threadIdx.x;
    int b  = blockIdx.z;
    int o0 = blockIdx.x * 64;
    int c0 = blockIdx.y * 64;
    float acc[4][4] = {};
    int m0  = (tid >> 4) << 2;   // c sub
    int nn0 = (tid & 15) << 2;   // o sub

    for (int it = 0; it < NPT; it += 32) {
        __syncthreads();
#pragma unroll
        for (int t = 0; t < 2; t++) {
            int f = tid*2 + t;
            int r = f >> 3, k4 = (f & 7) << 2;
            float4 v = make_float4(0.f,0.f,0.f,0.f);
            if (it + k4 < NPT)
                v = *(const float4*)&V[((size_t)b*CCH + c0 + r)*NPT + it + k4];
            *(float4*)&As[r][k4] = v;
            float4 p = make_float4(0.f,0.f,0.f,0.f);
            int o = o0 + r;
            if (o < NPT && it + k4 < NPT)
                p = *(const float4*)&P[((size_t)b*NPT + o)*NPT + it + k4];
            *(float4*)&Bs[r][k4] = p;
        }
        __syncthreads();
#pragma unroll
        for (int kq = 0; kq < 32; kq += 4) {
            float4 a[4], bb[4];
#pragma unroll
            for (int mi = 0; mi < 4; mi++) a[mi]  = *(const float4*)&As[m0 + mi][kq];
#pragma unroll
            for (int ni = 0; ni < 4; ni++) bb[ni] = *(const float4*)&Bs[nn0 + ni][kq];
#pragma unroll
            for (int mi = 0; mi < 4; mi++)
#pragma unroll
                for (int ni = 0; ni < 4; ni++)
                    acc[mi][ni] += a[mi].x*bb[ni].x + a[mi].y*bb[ni].y
                                 + a[mi].z*bb[ni].z + a[mi].w*bb[ni].w;
        }
    }

#pragma unroll
    for (int mi = 0; mi < 4; mi++) {
        int c = c0 + m0 + mi;
#pragma unroll
        for (int ni = 0; ni < 4; ni++) {
            int o = o0 + nn0 + ni;
            if (o < NPT)
                M[((size_t)b*CCH + c)*NPT + o] = acc[mi][ni];
        }
    }
}

// ---------------- normalized features -> out[B*N ...] ----------------
__global__ void norm_head_kernel(const float* __restrict__ X, float* __restrict__ out)
{
    int idx = blockIdx.x * blockDim.x + threadIdx.x;
    if (idx >= BB*NPT) return;
    int b = idx / NPT, n = idx - b*NPT;
    float ss = 0.f;
    for (int c = 0; c < CCH; c++) {
        float v = X[((size_t)b*CCH + c)*NPT + n];
        ss += v*v;
    }
    float inv = 1.f / fmaxf(sqrtf(ss), 1e-12f);
    float* dst = out + BB*NPT;
    for (int c = 0; c < CCH; c++) {
        size_t oi = ((size_t)b*CCH + c)*NPT + n;
        dst[oi] = X[oi] * inv;
    }
}

// ======================= host launcher =======================
extern "C" void kernel_launch(void* const* d_in, const int* in_sizes, int n_in,
                              void* d_out, int out_size)
{
    const float* corr    = (const float*)d_in[0];
    const float* src     = (const float*)d_in[1];
    const float* tgt     = (const float*)d_in[2];
    const float* iW      = (const float*)d_in[3];
    const float* ib      = (const float*)d_in[4];
    const float* pcnW    = (const float*)d_in[5];
    const float* pcnb    = (const float*)d_in[6];
    const float* pcng    = (const float*)d_in[7];
    const float* pcnbeta = (const float*)d_in[8];
    const float* qW  = (const float*)d_in[9];  const float* qb  = (const float*)d_in[10];
    const float* kW  = (const float*)d_in[11]; const float* kb  = (const float*)d_in[12];
    const float* vW  = (const float*)d_in[13]; const float* vb  = (const float*)d_in[14];
    const float* m1W = (const float*)d_in[15]; const float* m1b = (const float*)d_in[16];
    const float* m1g = (const float*)d_in[17]; const float* m1beta = (const float*)d_in[18];
    const float* m2W = (const float*)d_in[19]; const float* m2b = (const float*)d_in[20];
    const float* m2g = (const float*)d_in[21]; const float* m2beta = (const float*)d_in[22];
    const float* m3W = (const float*)d_in[23]; const float* m3b = (const float*)d_in[24];
    const float* c1W = (const float*)d_in[25]; const float* c1b = (const float*)d_in[26];
    const float* c2W = (const float*)d_in[27]; const float* c2b = (const float*)d_in[28];
    const float* c3W = (const float*)d_in[29]; const float* c3b = (const float*)d_in[30];
    float* out = (float*)d_out;

    float *x, *y, *q, *k, *v, *m, *h, *P, *scl, *shf;
    cudaGetSymbolAddress((void**)&x,   g_x);
    cudaGetSymbolAddress((void**)&y,   g_y);
    cudaGetSymbolAddress((void**)&q,   g_q);
    cudaGetSymbolAddress((void**)&k,   g_k);
    cudaGetSymbolAddress((void**)&v,   g_v);
    cudaGetSymbolAddress((void**)&m,   g_m);
    cudaGetSymbolAddress((void**)&h,   g_h);
    cudaGetSymbolAddress((void**)&P,   g_P);
    cudaGetSymbolAddress((void**)&scl, g_scl);
    cudaGetSymbolAddress((void**)&shf, g_shf);

    const int nT = (NPT + 63) / 64;   // 47
    dim3 blk(256);

    init_conv_kernel<<<(BB*NPT + 127)/128, 128>>>(corr, iW, ib, x);

    for (int l = 0; l < LL; l++) {
        // PointCN: x = relu(bn(conv(x)))
        conv_kernel<false,false><<<dim3(nT,2,BB), blk>>>(x, pcnW + (size_t)l*CCH*CCH, pcnb + l*CCH, nullptr, y, CCH, CCH);
        bn_stats_kernel<<<CCH, 256>>>(y, pcng + l*CCH, pcnbeta + l*CCH, scl, shf, CCH);
        affine_relu_kernel<<<(BB*CCH*NPT + 255)/256, 256>>>(y, scl, shf, x, CCH);

        // Q, K, V
        conv_kernel<false,false><<<dim3(nT,2,BB), blk>>>(x, qW + (size_t)l*CCH*CCH, qb + l*CCH, nullptr, q, CCH, CCH);
        conv_kernel<false,false><<<dim3(nT,2,BB), blk>>>(x, kW + (size_t)l*CCH*CCH, kb + l*CCH, nullptr, k, CCH, CCH);
        conv_kernel<false,false><<<dim3(nT,2,BB), blk>>>(x, vW + (size_t)l*CCH*CCH, vb + l*CCH, nullptr, v, CCH, CCH);

        // attention
        gemm_scores_kernel<<<dim3(nT,nT,BB), blk>>>(q, k, src, tgt, P);
        softmax_kernel<<<dim3(NPT,BB), blk>>>(P);
        gemm_msg_kernel<<<dim3(nT,2,BB), blk>>>(v, P, m);

        // msg MLP
        conv_kernel<false,false><<<dim3(nT,1,BB), blk>>>(m, m1W + (size_t)l*CH*CCH, m1b + l*CH, nullptr, y, CCH, CH);
        bn_stats_kernel<<<CH, 256>>>(y, m1g + l*CH, m1beta + l*CH, scl, shf, CH);
        affine_relu_kernel<<<(BB*CH*NPT + 255)/256, 256>>>(y, scl, shf, h, CH);

        conv_kernel<false,false><<<dim3(nT,1,BB), blk>>>(h, m2W + (size_t)l*CH*CH, m2b + l*CH, nullptr, y, CH, CH);
        bn_stats_kernel<<<CH, 256>>>(y, m2g + l*CH, m2beta + l*CH, scl, shf, CH);
        affine_relu_kernel<<<(BB*CH*NPT + 255)/256, 256>>>(y, scl, shf, m, CH);

        // m3 + residual -> x
        conv_kernel<false,true><<<dim3(nT,2,BB), blk>>>(m, m3W + (size_t)l*CCH*CH, m3b + l*CCH, x, x, CH, CCH);
    }

    // outputs
    norm_head_kernel<<<(BB*NPT + 255)/256, 256>>>(x, out);
    conv_kernel<true,false><<<dim3(nT,1,BB), blk>>>(x, c1W, c1b, nullptr, h, CCH, 32);
    conv_kernel<true,false><<<dim3(nT,1,BB), blk>>>(h, c2W, c2b, nullptr, y, 32, 32);
    conv_kernel<false,false><<<dim3(nT,1,BB), blk>>>(y, c3W, c3b, nullptr, out, 32, 1);
}

// round 3
// speedup vs baseline: 1.0404x; 1.0404x over previous
#include <cuda_runtime.h>
#include <math.h>

#define NPT 3000
#define BB 2
#define CCH 128
#define CH 64
#define LL 6
#define EPSBN 1e-5f
#define ATT_SCALE 0.08838834764831845f  // 1/sqrt(128)
#define MSPLIT 4
#define MCHUNK 752

typedef unsigned long long ull;

__device__ __forceinline__ void ffma2(ull &d, ull a, ull b) {
    asm("fma.rn.f32x2 %0, %1, %2, %0;" : "+l"(d) : "l"(a), "l"(b));
}
__device__ __forceinline__ float2 unp(ull v) {
    unsigned lo, hi;
    asm("mov.b64 {%0,%1}, %2;" : "=r"(lo), "=r"(hi) : "l"(v));
    return make_float2(__uint_as_float(lo), __uint_as_float(hi));
}
__device__ __forceinline__ ull d2u(double d) { return __double_as_longlong(d); }
__device__ __forceinline__ float sqrt_approx(float x) {
    float r; asm("sqrt.approx.f32 %0, %1;" : "=f"(r) : "f"(x)); return r;
}

// ---------------- device scratch ----------------
__device__ float g_x[BB*CCH*NPT];
__device__ float g_y[BB*CCH*NPT];
__device__ float g_q[BB*CCH*NPT];
__device__ float g_k[BB*CCH*NPT];
__device__ float g_v[BB*CCH*NPT];
__device__ float g_h[BB*CCH*NPT];
__device__ float g_Mp[(size_t)MSPLIT*BB*CCH*NPT];
__device__ float g_P[(size_t)BB*NPT*NPT];
__device__ float g_SC[(size_t)BB*NPT*NPT];
__device__ float g_scl[CCH],  g_shf[CCH];
__device__ float g_scl1[CCH], g_shf1[CCH];
__device__ float g_scl2[CCH], g_shf2[CCH];

// ---------------- init embedding ----------------
__global__ void init_conv_kernel(const float* __restrict__ corr, const float* __restrict__ W,
                                 const float* __restrict__ bias, float* __restrict__ X)
{
    __shared__ float Ws[CCH*6];
    __shared__ float bs[CCH];
    int tid = threadIdx.x;
    for (int i = tid; i < CCH*6; i += blockDim.x) Ws[i] = W[i];
    for (int i = tid; i < CCH;   i += blockDim.x) bs[i] = bias[i];
    __syncthreads();
    int idx = blockIdx.x * blockDim.x + tid;
    if (idx >= BB*NPT) return;
    int b = idx / NPT, n = idx - b*NPT;
    float cp[6];
#pragma unroll
    for (int j = 0; j < 6; j++) cp[j] = corr[(size_t)idx*6 + j];
    for (int co = 0; co < CCH; co++) {
        float a = bs[co];
#pragma unroll
        for (int j = 0; j < 6; j++) a += Ws[co*6 + j] * cp[j];
        X[((size_t)b*CCH + co)*NPT + n] = a;
    }
}

// ---------------- SC precompute: SC[b,o,i] = max(0,1-(ds-dt)^2) * ATT_SCALE ----------------
__global__ void __launch_bounds__(256) sc_kernel(const float* __restrict__ src,
                                                 const float* __restrict__ tgt,
                                                 float* __restrict__ SC)
{
    __shared__ float pO[128][6];
    __shared__ float pI[128][6];
    int tid = threadIdx.x;
    int b = blockIdx.z;
    int o0 = blockIdx.y << 7, i0 = blockIdx.x << 7;
    {
        int r = tid & 127;
        int n = (tid < 128 ? o0 : i0) + r;
        float* dst = (tid < 128) ? pO[r] : pI[r];
        if (n < NPT) {
#pragma unroll
            for (int j = 0; j < 3; j++) {
                dst[j]     = src[((size_t)b*NPT + n)*3 + j];
                dst[3 + j] = tgt[((size_t)b*NPT + n)*3 + j];
            }
        } else {
#pragma unroll
            for (int j = 0; j < 6; j++) dst[j] = 0.f;
        }
    }
    __syncthreads();
    int ty = tid >> 4, tx = tid & 15;
    int ob = ty << 3, ib = tx << 3;
    int icol = i0 + ib;
    if (icol >= NPT) return;
#pragma unroll
    for (int mi = 0; mi < 8; mi++) {
        int o = o0 + ob + mi;
        if (o >= NPT) continue;
        float out[8];
#pragma unroll
        for (int ni = 0; ni < 8; ni++) {
            float dx = pO[ob+mi][0] - pI[ib+ni][0];
            float dy = pO[ob+mi][1] - pI[ib+ni][1];
            float dz = pO[ob+mi][2] - pI[ib+ni][2];
            float ds = sqrt_approx(dx*dx + dy*dy + dz*dz);
            dx = pO[ob+mi][3] - pI[ib+ni][3];
            dy = pO[ob+mi][4] - pI[ib+ni][4];
            dz = pO[ob+mi][5] - pI[ib+ni][5];
            float dt = sqrt_approx(dx*dx + dy*dy + dz*dz);
            float d = ds - dt;
            out[ni] = fmaxf(1.f - d*d, 0.f) * ATT_SCALE;
        }
        size_t off = ((size_t)b*NPT + o)*NPT + icol;
        *(float4*)&SC[off]     = make_float4(out[0], out[1], out[2], out[3]);
        *(float4*)&SC[off + 4] = make_float4(out[4], out[5], out[6], out[7]);
    }
}

// ---------------- scores: P[b,o,i] = SC[b,o,i] * sum_c Q[c,o]K[c,i] ----------------
// 128x128 tile, 256 threads, 8x8/thread, f32x2 packed along i, Q duplicated in smem.
__global__ void __launch_bounds__(256) gemm_scores_kernel(const float* __restrict__ Q,
                                                          const float* __restrict__ K,
                                                          const float* __restrict__ SC,
                                                          float* __restrict__ P)
{
    __shared__ float Qs[16][256];   // o duplicated: Qs[kk][2o],[2o+1]
    __shared__ float Ks[16][128];
    int tid = threadIdx.x;
    int b = blockIdx.z, o0 = blockIdx.y << 7, i0 = blockIdx.x << 7;
    int ty = tid >> 4, tx = tid & 15;
    ull acc[8][4];
#pragma unroll
    for (int i = 0; i < 8; i++)
#pragma unroll
        for (int j = 0; j < 4; j++) acc[i][j] = 0ull;

#pragma unroll 1
    for (int kt = 0; kt < CCH; kt += 16) {
        __syncthreads();
#pragma unroll
        for (int t = 0; t < 2; t++) {
            int idx = tid + (t << 8);
            int kk = idx >> 5, j4 = (idx & 31) << 2;
            float4 qv = make_float4(0.f,0.f,0.f,0.f);
            float4 kv = make_float4(0.f,0.f,0.f,0.f);
            if (o0 + j4 < NPT) qv = *(const float4*)&Q[((size_t)(b*CCH + kt + kk))*NPT + o0 + j4];
            if (i0 + j4 < NPT) kv = *(const float4*)&K[((size_t)(b*CCH + kt + kk))*NPT + i0 + j4];
            *(float4*)&Qs[kk][2*j4]     = make_float4(qv.x, qv.x, qv.y, qv.y);
            *(float4*)&Qs[kk][2*j4 + 4] = make_float4(qv.z, qv.z, qv.w, qv.w);
            *(float4*)&Ks[kk][j4] = kv;
        }
        __syncthreads();
#pragma unroll
        for (int kk = 0; kk < 16; kk++) {
            const double2* qp = (const double2*)&Qs[kk][ty << 4];
            const double2* kp = (const double2*)&Ks[kk][tx << 3];
            double2 q0 = qp[0], q1 = qp[1], q2 = qp[2], q3 = qp[3];
            double2 k0 = kp[0], k1 = kp[1];
            ull a[8]   = {d2u(q0.x), d2u(q0.y), d2u(q1.x), d2u(q1.y),
                          d2u(q2.x), d2u(q2.y), d2u(q3.x), d2u(q3.y)};
            ull bb4[4] = {d2u(k0.x), d2u(k0.y), d2u(k1.x), d2u(k1.y)};
#pragma unroll
            for (int mi = 0; mi < 8; mi++)
#pragma unroll
                for (int ni = 0; ni < 4; ni++)
                    ffma2(acc[mi][ni], a[mi], bb4[ni]);
        }
    }

    int icol = i0 + (tx << 3);
    if (icol >= NPT) return;
    int orow = o0 + (ty << 3);
#pragma unroll
    for (int mi = 0; mi < 8; mi++) {
        int o = orow + mi;
        if (o >= NPT) continue;
        size_t off = ((size_t)b*NPT + o)*NPT + icol;
        float4 s0 = *(const float4*)&SC[off];
        float4 s1 = *(const float4*)&SC[off + 4];
        float2 f0 = unp(acc[mi][0]), f1 = unp(acc[mi][1]);
        float2 f2 = unp(acc[mi][2]), f3 = unp(acc[mi][3]);
        *(float4*)&P[off]     = make_float4(f0.x*s0.x, f0.y*s0.y, f1.x*s0.z, f1.y*s0.w);
        *(float4*)&P[off + 4] = make_float4(f2.x*s1.x, f2.y*s1.y, f3.x*s1.z, f3.y*s1.w);
    }
}

// ---------------- row softmax in-place ----------------
__global__ void softmax_kernel(float* __restrict__ P)
{
    __shared__ float row[NPT];
    __shared__ float red[9];
    int o = blockIdx.x, b = blockIdx.y;
    int tid = threadIdx.x;
    float* base = P + ((size_t)b*NPT + o)*NPT;

    float mx = -3.4e38f;
    for (int i = tid*4; i < NPT; i += 1024) {
        float4 v = *(const float4*)&base[i];
        *(float4*)&row[i] = v;
        mx = fmaxf(mx, fmaxf(fmaxf(v.x, v.y), fmaxf(v.z, v.w)));
    }
#pragma unroll
    for (int s = 16; s; s >>= 1) mx = fmaxf(mx, __shfl_xor_sync(0xffffffffu, mx, s));
    int wid = tid >> 5, lane = tid & 31;
    if (lane == 0) red[wid] = mx;
    __syncthreads();
    if (tid == 0) {
        float m = red[0];
        for (int w = 1; w < 8; w++) m = fmaxf(m, red[w]);
        red[8] = m;
    }
    __syncthreads();
    mx = red[8];

    float sum = 0.f;
    for (int i = tid*4; i < NPT; i += 1024) {
        float4 v = *(float4*)&row[i];
        v.x = __expf(v.x - mx); v.y = __expf(v.y - mx);
        v.z = __expf(v.z - mx); v.w = __expf(v.w - mx);
        *(float4*)&row[i] = v;
        sum += v.x + v.y + v.z + v.w;
    }
#pragma unroll
    for (int s = 16; s; s >>= 1) sum += __shfl_xor_sync(0xffffffffu, sum, s);
    __syncthreads();
    if (lane == 0) red[wid] = sum;
    __syncthreads();
    if (tid == 0) {
        float s = 0.f;
        for (int w = 0; w < 8; w++) s += red[w];
        red[8] = s;
    }
    __syncthreads();
    float inv = 1.f / red[8];

    for (int i = tid*4; i < NPT; i += 1024) {
        float4 v = *(float4*)&row[i];
        v.x *= inv; v.y *= inv; v.z *= inv; v.w *= inv;
        *(float4*)&base[i] = v;
    }
}

// ---------------- msg (NT, split-K): Mp[s][b,c,o] = sum_{i in split s} V[b,c,i] P[b,o,i] ----
// 128c x 128o tile, 256 threads, 8x8/thread, f32x2 packed along c, P duplicated in smem.
__global__ void __launch_bounds__(256) gemm_msg_kernel(const float* __restrict__ V,
                                                       const float* __restrict__ P,
                                                       float* __restrict__ Mp)
{
    __shared__ float Vs[16][128];
    __shared__ float Ps[16][256];   // o duplicated
    int tid = threadIdx.x;
    int b = blockIdx.z, s = blockIdx.y, o0 = blockIdx.x << 7;
    int ty = tid >> 4, tx = tid & 15;
    int ib0 = s * MCHUNK;
    int ilim = min(ib0 + MCHUNK, NPT);
    ull acc[4][8];
#pragma unroll
    for (int i = 0; i < 4; i++)
#pragma unroll
        for (int j = 0; j < 8; j++) acc[i][j] = 0ull;

#pragma unroll 1
    for (int ib = ib0; ib < ib0 + MCHUNK; ib += 16) {
        __syncthreads();
#pragma unroll
        for (int t = 0; t < 2; t++) {
            int idx = tid + (t << 8);
            int r = idx >> 2;              // 0..127
            int kk4 = (idx & 3) << 2;
            int ii = ib + kk4;
            float4 v = make_float4(0.f,0.f,0.f,0.f);
            if (ii < ilim) v = *(const float4*)&V[((size_t)(b*CCH + r))*NPT + ii];
            Vs[kk4][r] = v.x; Vs[kk4+1][r] = v.y; Vs[kk4+2][r] = v.z; Vs[kk4+3][r] = v.w;
            float4 p = make_float4(0.f,0.f,0.f,0.f);
            int oo = o0 + r;
            if (ii < ilim && oo < NPT) p = *(const float4*)&P[((size_t)b*NPT + oo)*NPT + ii];
            Ps[kk4][2*r]   = p.x; Ps[kk4][2*r+1]   = p.x;
            Ps[kk4+1][2*r] = p.y; Ps[kk4+1][2*r+1] = p.y;
            Ps[kk4+2][2*r] = p.z; Ps[kk4+2][2*r+1] = p.z;
            Ps[kk4+3][2*r] = p.w; Ps[kk4+3][2*r+1] = p.w;
        }
        __syncthreads();
#pragma unroll
        for (int kk = 0; kk < 16; kk++) {
            const double2* vp = (const double2*)&Vs[kk][ty << 3];
            const double2* pp = (const double2*)&Ps[kk][tx << 4];
            double2 v0 = vp[0], v1 = vp[1];
            double2 p0 = pp[0], p1 = pp[1], p2 = pp[2], p3 = pp[3];
            ull a[4]  = {d2u(v0.x), d2u(v0.y), d2u(v1.x), d2u(v1.y)};
            ull bd[8] = {d2u(p0.x), d2u(p0.y), d2u(p1.x), d2u(p1.y),
                         d2u(p2.x), d2u(p2.y), d2u(p3.x), d2u(p3.y)};
#pragma unroll
            for (int cp = 0; cp < 4; cp++)
#pragma unroll
                for (int oi = 0; oi < 8; oi++)
                    ffma2(acc[cp][oi], a[cp], bd[oi]);
        }
    }

    int oc = o0 + (tx << 3);
    if (oc >= NPT) return;
    float* base = Mp + ((size_t)(s*BB + b))*CCH*NPT;
#pragma unroll
    for (int cp = 0; cp < 4; cp++) {
        int c = (ty << 3) + (cp << 1);
        float lo[8], hi[8];
#pragma unroll
        for (int oi = 0; oi < 8; oi++) { float2 f = unp(acc[cp][oi]); lo[oi] = f.x; hi[oi] = f.y; }
        *(float4*)&base[(size_t)c*NPT + oc]       = make_float4(lo[0], lo[1], lo[2], lo[3]);
        *(float4*)&base[(size_t)c*NPT + oc + 4]   = make_float4(lo[4], lo[5], lo[6], lo[7]);
        *(float4*)&base[(size_t)(c+1)*NPT + oc]     = make_float4(hi[0], hi[1], hi[2], hi[3]);
        *(float4*)&base[(size_t)(c+1)*NPT + oc + 4] = make_float4(hi[4], hi[5], hi[6], hi[7]);
    }
}

// ---------------- pointwise conv with fused input transforms ----------------
// INMODE: 0 = plain, 1 = relu(scl*x+shf) on input, 2 = sum of MSPLIT partial buffers
template<int INMODE, bool RELU, bool RESID>
__global__ void __launch_bounds__(256) conv_kernel(const float* __restrict__ X,
        const float* __restrict__ W, const float* __restrict__ bias,
        const float* __restrict__ scl, const float* __restrict__ shf,
        const float* __restrict__ R, float* __restrict__ Y, int Cin, int Cout)
{
    __shared__ float Ws[16][128];   // co duplicated
    __shared__ float Xs[16][64];
    __shared__ float sA[CCH], sB[CCH];
    int tid = threadIdx.x;
    int b = blockIdx.z, c0 = blockIdx.y << 6, n0 = blockIdx.x << 6;
    if (INMODE == 1) {
        if (tid < Cin) { sA[tid] = scl[tid]; sB[tid] = shf[tid]; }
    }
    int ty = tid >> 4, tx = tid & 15;
    ull acc[4][2];
#pragma unroll
    for (int i = 0; i < 4; i++) { acc[i][0] = 0ull; acc[i][1] = 0ull; }

#pragma unroll 1
    for (int kt = 0; kt < Cin; kt += 16) {
        __syncthreads();
        {
            int m = tid >> 2, kk4 = (tid & 3) << 2;
            float4 w = make_float4(0.f,0.f,0.f,0.f);
            if (c0 + m < Cout) w = *(const float4*)&W[(size_t)(c0 + m)*Cin + kt + kk4];
            Ws[kk4][2*m] = w.x;   Ws[kk4][2*m+1] = w.x;
            Ws[kk4+1][2*m] = w.y; Ws[kk4+1][2*m+1] = w.y;
            Ws[kk4+2][2*m] = w.z; Ws[kk4+2][2*m+1] = w.z;
            Ws[kk4+3][2*m] = w.w; Ws[kk4+3][2*m+1] = w.w;
        }
        {
            int kk = tid >> 4, j4 = (tid & 15) << 2;
            int ci = kt + kk;
            float4 v = make_float4(0.f,0.f,0.f,0.f);
            if (n0 + j4 < NPT) {
                size_t off = ((size_t)(b*Cin + ci))*NPT + n0 + j4;
                if (INMODE == 2) {
                    const size_t str = (size_t)BB*CCH*NPT;
                    float4 a0 = *(const float4*)&X[off];
                    float4 a1 = *(const float4*)&X[off + str];
                    float4 a2 = *(const float4*)&X[off + 2*str];
                    float4 a3 = *(const float4*)&X[off + 3*str];
                    v = make_float4(a0.x+a1.x+a2.x+a3.x, a0.y+a1.y+a2.y+a3.y,
                                    a0.z+a1.z+a2.z+a3.z, a0.w+a1.w+a2.w+a3.w);
                } else {
                    v = *(const float4*)&X[off];
                }
                if (INMODE == 1) {
                    float sa = sA[ci], sb = sB[ci];
                    v.x = fmaxf(fmaf(sa, v.x, sb), 0.f);
                    v.y = fmaxf(fmaf(sa, v.y, sb), 0.f);
                    v.z = fmaxf(fmaf(sa, v.z, sb), 0.f);
                    v.w = fmaxf(fmaf(sa, v.w, sb), 0.f);
                }
            }
            *(float4*)&Xs[kk][j4] = v;
        }
        __syncthreads();
#pragma unroll
        for (int kk = 0; kk < 16; kk++) {
            const double2* wp = (const double2*)&Ws[kk][ty << 3];
            double2 w0 = wp[0], w1 = wp[1];
            ull a[4] = {d2u(w0.x), d2u(w0.y), d2u(w1.x), d2u(w1.y)};
            const double2* xp = (const double2*)&Xs[kk][tx << 2];
            double2 x0 = xp[0];
            ull b0 = d2u(x0.x), b1 = d2u(x0.y);
#pragma unroll
            for (int mi = 0; mi < 4; mi++) {
                ffma2(acc[mi][0], a[mi], b0);
                ffma2(acc[mi][1], a[mi], b1);
            }
        }
    }

    int n = n0 + (tx << 2);
    if (n >= NPT) return;
#pragma unroll
    for (int mi = 0; mi < 4; mi++) {
        int co = c0 + (ty << 2) + mi;
        if (co >= Cout) continue;
        float bv = bias[co];
        float2 f0 = unp(acc[mi][0]), f1 = unp(acc[mi][1]);
        float4 o4 = make_float4(f0.x + bv, f0.y + bv, f1.x + bv, f1.y + bv);
        size_t off = ((size_t)(b*Cout + co))*NPT + n;
        if (RESID) {
            float4 r = *(const float4*)&R[off];
            o4.x += r.x; o4.y += r.y; o4.z += r.z; o4.w += r.w;
        }
        if (RELU) {
            o4.x = fmaxf(o4.x, 0.f); o4.y = fmaxf(o4.y, 0.f);
            o4.z = fmaxf(o4.z, 0.f); o4.w = fmaxf(o4.w, 0.f);
        }
        *(float4*)&Y[off] = o4;
    }
}

// ---------------- BN stats -> per-channel affine ----------------
__global__ void bn_stats_kernel(const float* __restrict__ Y, const float* __restrict__ g,
                                const float* __restrict__ beta, float* __restrict__ scl,
                                float* __restrict__ shf, int Cc)
{
    __shared__ float s1[256], s2[256];
    int c = blockIdx.x, tid = threadIdx.x;
    float a = 0.f, q = 0.f;
    for (int bb = 0; bb < BB; bb++) {
        const float* row = Y + ((size_t)(bb*Cc + c))*NPT;
        for (int i = tid*4; i < NPT; i += 1024) {
            float4 v = *(const float4*)&row[i];
            a += v.x + v.y + v.z + v.w;
            q += v.x*v.x + v.y*v.y + v.z*v.z + v.w*v.w;
        }
    }
    s1[tid] = a; s2[tid] = q;
    __syncthreads();
    for (int o = 128; o > 0; o >>= 1) {
        if (tid < o) { s1[tid] += s1[tid+o]; s2[tid] += s2[tid+o]; }
        __syncthreads();
    }
    if (tid == 0) {
        float inv = 1.f / (float)(BB*NPT);
        float m = s1[0] * inv;
        float var = s2[0] * inv - m*m;
        float rs = rsqrtf(var + EPSBN);
        scl[c] = g[c] * rs;
        shf[c] = beta[c] - m * g[c] * rs;
    }
}

__global__ void affine_relu_kernel(const float* __restrict__ Y, const float* __restrict__ scl,
                                   const float* __restrict__ shf, float* __restrict__ X, int Cc)
{
    int i = blockIdx.x * blockDim.x + threadIdx.x;  // float4 index
    int total = BB * Cc * (NPT/4);
    if (i >= total) return;
    int c = (i / (NPT/4)) % Cc;
    float4 v = ((const float4*)Y)[i];
    float sa = scl[c], sb = shf[c];
    v.x = fmaxf(fmaf(sa, v.x, sb), 0.f);
    v.y = fmaxf(fmaf(sa, v.y, sb), 0.f);
    v.z = fmaxf(fmaf(sa, v.z, sb), 0.f);
    v.w = fmaxf(fmaf(sa, v.w, sb), 0.f);
    ((float4*)X)[i] = v;
}

// ---------------- normalized features ----------------
__global__ void norm_head_kernel(const float* __restrict__ X, float* __restrict__ out)
{
    int idx = blockIdx.x * blockDim.x + threadIdx.x;
    if (idx >= BB*NPT) return;
    int b = idx / NPT, n = idx - b*NPT;
    float ss = 0.f;
    for (int c = 0; c < CCH; c++) {
        float v = X[((size_t)b*CCH + c)*NPT + n];
        ss += v*v;
    }
    float inv = 1.f / fmaxf(sqrtf(ss), 1e-12f);
    float* dst = out + BB*NPT;
    for (int c = 0; c < CCH; c++) {
        size_t oi = ((size_t)b*CCH + c)*NPT + n;
        dst[oi] = X[oi] * inv;
    }
}

// ======================= host launcher =======================
extern "C" void kernel_launch(void* const* d_in, const int* in_sizes, int n_in,
                              void* d_out, int out_size)
{
    const float* corr    = (const float*)d_in[0];
    const float* src     = (const float*)d_in[1];
    const float* tgt     = (const float*)d_in[2];
    const float* iW      = (const float*)d_in[3];
    const float* ib      = (const float*)d_in[4];
    const float* pcnW    = (const float*)d_in[5];
    const float* pcnb    = (const float*)d_in[6];
    const float* pcng    = (const float*)d_in[7];
    const float* pcnbeta = (const float*)d_in[8];
    const float* qW  = (const float*)d_in[9];  const float* qb  = (const float*)d_in[10];
    const float* kW  = (const float*)d_in[11]; const float* kb  = (const float*)d_in[12];
    const float* vW  = (const float*)d_in[13]; const float* vb  = (const float*)d_in[14];
    const float* m1W = (const float*)d_in[15]; const float* m1b = (const float*)d_in[16];
    const float* m1g = (const float*)d_in[17]; const float* m1beta = (const float*)d_in[18];
    const float* m2W = (const float*)d_in[19]; const float* m2b = (const float*)d_in[20];
    const float* m2g = (const float*)d_in[21]; const float* m2beta = (const float*)d_in[22];
    const float* m3W = (const float*)d_in[23]; const float* m3b = (const float*)d_in[24];
    const float* c1W = (const float*)d_in[25]; const float* c1b = (const float*)d_in[26];
    const float* c2W = (const float*)d_in[27]; const float* c2b = (const float*)d_in[28];
    const float* c3W = (const float*)d_in[29]; const float* c3b = (const float*)d_in[30];
    float* out = (float*)d_out;

    float *x, *y, *q, *k, *v, *h, *Mp, *P, *SC;
    float *scl, *shf, *scl1, *shf1, *scl2, *shf2;
    cudaGetSymbolAddress((void**)&x,   g_x);
    cudaGetSymbolAddress((void**)&y,   g_y);
    cudaGetSymbolAddress((void**)&q,   g_q);
    cudaGetSymbolAddress((void**)&k,   g_k);
    cudaGetSymbolAddress((void**)&v,   g_v);
    cudaGetSymbolAddress((void**)&h,   g_h);
    cudaGetSymbolAddress((void**)&Mp,  g_Mp);
    cudaGetSymbolAddress((void**)&P,   g_P);
    cudaGetSymbolAddress((void**)&SC,  g_SC);
    cudaGetSymbolAddress((void**)&scl,  g_scl);  cudaGetSymbolAddress((void**)&shf,  g_shf);
    cudaGetSymbolAddress((void**)&scl1, g_scl1); cudaGetSymbolAddress((void**)&shf1, g_shf1);
    cudaGetSymbolAddress((void**)&scl2, g_scl2); cudaGetSymbolAddress((void**)&shf2, g_shf2);

    const int nT64  = (NPT + 63) / 64;     // 47
    const int nT128 = (NPT + 127) / 128;   // 24
    dim3 blk(256);

    init_conv_kernel<<<(BB*NPT + 127)/128, 128>>>(corr, iW, ib, x);
    sc_kernel<<<dim3(nT128, nT128, BB), blk>>>(src, tgt, SC);

    for (int l = 0; l < LL; l++) {
        // PointCN: x = relu(bn(conv(x)))
        conv_kernel<0,false,false><<<dim3(nT64,2,BB), blk>>>(x, pcnW + (size_t)l*CCH*CCH, pcnb + l*CCH,
                                                             nullptr, nullptr, nullptr, y, CCH, CCH);
        bn_stats_kernel<<<CCH, 256>>>(y, pcng + l*CCH, pcnbeta + l*CCH, scl, shf, CCH);
        affine_relu_kernel<<<(BB*CCH*(NPT/4) + 255)/256, 256>>>(y, scl, shf, x, CCH);

        // Q, K, V projections
        conv_kernel<0,false,false><<<dim3(nT64,2,BB), blk>>>(x, qW + (size_t)l*CCH*CCH, qb + l*CCH,
                                                             nullptr, nullptr, nullptr, q, CCH, CCH);
        conv_kernel<0,false,false><<<dim3(nT64,2,BB), blk>>>(x, kW + (size_t)l*CCH*CCH, kb + l*CCH,
                                                             nullptr, nullptr, nullptr, k, CCH, CCH);
        conv_kernel<0,false,false><<<dim3(nT64,2,BB), blk>>>(x, vW + (size_t)l*CCH*CCH, vb + l*CCH,
                                                             nullptr, nullptr, nullptr, v, CCH, CCH);

        // attention
        gemm_scores_kernel<<<dim3(nT128, nT128, BB), blk>>>(q, k, SC, P);
        softmax_kernel<<<dim3(NPT, BB), blk>>>(P);
        gemm_msg_kernel<<<dim3(nT128, MSPLIT, BB), blk>>>(v, P, Mp);

        // msg MLP (BN affines fused into next conv's loads)
        conv_kernel<2,false,false><<<dim3(nT64,1,BB), blk>>>(Mp, m1W + (size_t)l*CH*CCH, m1b + l*CH,
                                                             nullptr, nullptr, nullptr, y, CCH, CH);
        bn_stats_kernel<<<CH, 256>>>(y, m1g + l*CH, m1beta + l*CH, scl1, shf1, CH);
        conv_kernel<1,false,false><<<dim3(nT64,1,BB), blk>>>(y, m2W + (size_t)l*CH*CH, m2b + l*CH,
                                                             scl1, shf1, nullptr, h, CH, CH);
        bn_stats_kernel<<<CH, 256>>>(h, m2g + l*CH, m2beta + l*CH, scl2, shf2, CH);
        conv_kernel<1,false,true><<<dim3(nT64,2,BB), blk>>>(h, m3W + (size_t)l*CCH*CH, m3b + l*CCH,
                                                            scl2, shf2, x, x, CH, CCH);
    }

    // outputs
    norm_head_kernel<<<(BB*NPT + 255)/256, 256>>>(x, out);
    conv_kernel<0,true,false><<<dim3(nT64,1,BB), blk>>>(x, c1W, c1b, nullptr, nullptr, nullptr, h, CCH, 32);
    conv_kernel<0,true,false><<<dim3(nT64,1,BB), blk>>>(h, c2W, c2b, nullptr, nullptr, nullptr, y, 32, 32);
    conv_kernel<0,false,false><<<dim3(nT64,1,BB), blk>>>(y, c3W, c3b, nullptr, nullptr, nullptr, out, 32, 1);
}